// round 16
// baseline (speedup 1.0000x reference)
#include <cuda_runtime.h>
#include <cuda_bf16.h>
#include <cuda_fp16.h>
#include <cstdint>

#define BDIM 8
#define LDIM 256
#define CDIM 512
#define ODIM 512
#define MTOT (BDIM * LDIM)   // 2048
#define KSPL 1536            // 3*CDIM split-K
#define SROWP 72             // smem row stride (64 + 8 pad) bf16

// -------- scratch (static device globals; no allocation) --------
__device__ __align__(16) __nv_bfloat16 g_xt_s[MTOT * KSPL];   // relu(xt) split [hi,hi,lo]
__device__ __align__(16) __nv_bfloat16 g_xd_s[MTOT * KSPL];   // relu(xd) split [hi,hi,lo]
__device__ __align__(16) __nv_bfloat16 g_Wp_s[CDIM * KSPL];   // Wp^T split [hi,lo,hi]
__device__ __align__(16) __nv_bfloat16 g_Wc_s[CDIM * KSPL];   // Wc^T split [hi,lo,hi]
__device__ __align__(16) __nv_bfloat16 g_pt_s[MTOT * KSPL];   // pt split [hi,hi,lo]
__device__ __align__(16) __nv_bfloat16 g_pc_s[MTOT * KSPL];   // pc split [hi,lo,hi]
__device__ float g_scores[BDIM * LDIM * LDIM];
__device__ float g_Ssum[BDIM];
__device__ float g_cp[BDIM * CDIM];

// -------- transcendentals --------
__device__ __forceinline__ float sigmoid_fast(float x) {
    return __fdividef(1.0f, 1.0f + __expf(-x));
}
// packed-half tanh: 2 tanh per MUFU op
__device__ __forceinline__ float2 tanh2_f16(float a, float b) {
    __half2 h = __floats2half2_rn(a, b);
    uint32_t hin = *reinterpret_cast<uint32_t*>(&h);
    uint32_t r;
    asm("tanh.approx.f16x2 %0, %1;" : "=r"(r) : "r"(hin));
    __half2 o = *reinterpret_cast<__half2*>(&r);
    return __half22float2(o);
}

// -------- helpers --------
__device__ __forceinline__ uint32_t smem_u32(const void* p) {
    uint32_t a;
    asm("{ .reg .u64 t; cvta.to.shared.u64 t, %1; cvt.u32.u64 %0, t; }" : "=r"(a) : "l"(p));
    return a;
}
__device__ __forceinline__ void ldsm4(uint32_t* r, uint32_t addr) {
    asm volatile("ldmatrix.sync.aligned.m8n8.x4.shared.b16 {%0,%1,%2,%3}, [%4];"
                 : "=r"(r[0]), "=r"(r[1]), "=r"(r[2]), "=r"(r[3]) : "r"(addr));
}
__device__ __forceinline__ void mma_bf16(float* c, const uint32_t* a,
                                         uint32_t b0, uint32_t b1) {
    asm volatile(
        "mma.sync.aligned.m16n8k16.row.col.f32.bf16.bf16.f32 "
        "{%0,%1,%2,%3}, {%4,%5,%6,%7}, {%8,%9}, {%0,%1,%2,%3};"
        : "+f"(c[0]), "+f"(c[1]), "+f"(c[2]), "+f"(c[3])
        : "r"(a[0]), "r"(a[1]), "r"(a[2]), "r"(a[3]), "r"(b0), "r"(b1));
}
__device__ __forceinline__ void cp_async16(uint32_t dst, const void* src) {
    asm volatile("cp.async.ca.shared.global [%0], [%1], 16;" :: "r"(dst), "l"(src));
}
#define CP_COMMIT() asm volatile("cp.async.commit_group;" ::: "memory")
#define CP_WAIT1()  asm volatile("cp.async.wait_group 1;" ::: "memory")
#define CP_WAIT0()  asm volatile("cp.async.wait_group 0;" ::: "memory")

__device__ __forceinline__ void split2(float v, unsigned short& h, unsigned short& l) {
    __nv_bfloat16 hb = __float2bfloat16(v);
    __nv_bfloat16 lb = __float2bfloat16(v - __bfloat162float(hb));
    h = __bfloat16_as_ushort(hb);
    l = __bfloat16_as_ushort(lb);
}

// ============================================================
// HMMA mainloop: C[BM,64] += A[BM,K'] . B[64,K']^T over K'=1536, BK=64,
// 3-stage cp.async pipeline, ONE __syncthreads per chunk.
// ============================================================
template <int BM, int NWM, int NWN, int NT>
__device__ __forceinline__ void hmma_loop(
        const __nv_bfloat16* __restrict__ A0,
        const __nv_bfloat16* __restrict__ B0,
        __nv_bfloat16* sm, float (*acc)[4], int tid) {
    constexpr int MI = BM / NWM / 16;
    constexpr int NJ = 64 / NWN / 8;
    constexpr int NJ2 = NJ / 2;
    constexpr int STAGE = (BM + 64) * SROWP;
    constexpr int NLD = (BM + 64) * 8;
    constexpr int LPT = NLD / NT;
    constexpr int NCH = KSPL / 64;

    const int lane = tid & 31;
    const int warp = tid >> 5;
    const int wm = warp % NWM;
    const int wn = warp / NWM;
    const uint32_t base = smem_u32(sm);

    auto issue = [&](int s, int c) {
        #pragma unroll
        for (int q = 0; q < LPT; q++) {
            int idx = tid + q * NT;
            int matB = (idx >= BM * 8);
            int rem = matB ? (idx - BM * 8) : idx;
            int row = rem >> 3;
            int kq = rem & 7;
            const __nv_bfloat16* g = (matB ? B0 : A0) + (size_t)row * KSPL + c * 64 + kq * 8;
            uint32_t d = base + (uint32_t)(s * STAGE + matB * (BM * SROWP)
                                           + row * SROWP + kq * 8) * 2;
            cp_async16(d, g);
        }
        CP_COMMIT();
    };

    issue(0, 0);
    issue(1, 1);

    for (int c = 0; c < NCH; c++) {
        const int s = c % 3;
        if (c + 1 < NCH) CP_WAIT1(); else CP_WAIT0();
        __syncthreads();
        if (c + 2 < NCH) issue((c + 2) % 3, c + 2);

        const uint32_t aBase = base + (uint32_t)(s * STAGE) * 2;
        const uint32_t bBase = aBase + (uint32_t)(BM * SROWP) * 2;
        #pragma unroll
        for (int kk = 0; kk < 64; kk += 16) {
            uint32_t af[MI][4];
            #pragma unroll
            for (int im = 0; im < MI; im++) {
                int row = wm * (BM / NWM) + im * 16 + (lane & 15);
                ldsm4(af[im], aBase + (uint32_t)(row * SROWP + kk + (lane >> 4) * 8) * 2);
            }
            #pragma unroll
            for (int j2 = 0; j2 < NJ2; j2++) {
                uint32_t bfr[4];
                int row = wn * (64 / NWN) + j2 * 16 + (lane & 15);
                ldsm4(bfr, bBase + (uint32_t)(row * SROWP + kk + (lane >> 4) * 8) * 2);
                #pragma unroll
                for (int im = 0; im < MI; im++) {
                    mma_bf16(acc[im * NJ + 2 * j2 + 0], af[im], bfr[0], bfr[2]);
                    mma_bf16(acc[im * NJ + 2 * j2 + 1], af[im], bfr[1], bfr[3]);
                }
            }
        }
    }
    __syncthreads();
}

// ============================================================
// K0: init
// ============================================================
__global__ void init_kernel(const float* __restrict__ bf, float* __restrict__ out) {
    int idx = blockIdx.x * blockDim.x + threadIdx.x;
    if (idx < BDIM) g_Ssum[idx] = 0.0f;
    if (idx < BDIM * CDIM) {
        g_cp[idx] = 0.0f;
        out[idx] = bf[idx & (ODIM - 1)];
    }
}

// ============================================================
// K1: split X (with relu) -> [hi, hi, lo] bf16, K'=1536
// ============================================================
__global__ void split_x_kernel(const float* __restrict__ xt, const float* __restrict__ xd) {
    const float* X = blockIdx.z ? xd : xt;
    __nv_bfloat16* O = blockIdx.z ? g_xd_s : g_xt_s;
    int gid = blockIdx.x * blockDim.x + threadIdx.x;
    if (gid >= MTOT * CDIM / 4) return;
    int m = gid >> 7;
    int k4 = (gid & 127) * 4;
    float4 v = *reinterpret_cast<const float4*>(X + (size_t)m * CDIM + k4);
    float vv[4] = {fmaxf(v.x, 0.f), fmaxf(v.y, 0.f), fmaxf(v.z, 0.f), fmaxf(v.w, 0.f)};
    unsigned short h[4], l[4];
    #pragma unroll
    for (int i = 0; i < 4; i++) split2(vv[i], h[i], l[i]);
    uint2 hp = make_uint2((uint32_t)h[0] | ((uint32_t)h[1] << 16),
                          (uint32_t)h[2] | ((uint32_t)h[3] << 16));
    uint2 lp = make_uint2((uint32_t)l[0] | ((uint32_t)l[1] << 16),
                          (uint32_t)l[2] | ((uint32_t)l[3] << 16));
    size_t base = (size_t)m * KSPL + k4;
    *reinterpret_cast<uint2*>(O + base) = hp;
    *reinterpret_cast<uint2*>(O + base + CDIM) = hp;
    *reinterpret_cast<uint2*>(O + base + 2 * CDIM) = lp;
}

// ============================================================
// K2: split W with transpose: W[k,n] -> Wsplit[n,k'] segs [hi, lo, hi]
// ============================================================
__global__ void split_w_kernel(const float* __restrict__ Wp, const float* __restrict__ Wc) {
    const float* W = blockIdx.z ? Wc : Wp;
    __nv_bfloat16* O = blockIdx.z ? g_Wc_s : g_Wp_s;
    __shared__ float tile[32][33];
    int k0 = blockIdx.x * 32, n0 = blockIdx.y * 32;
    int tx = threadIdx.x, ty = threadIdx.y;
    tile[ty][tx] = W[(size_t)(k0 + ty) * CDIM + n0 + tx];
    __syncthreads();
    float v = tile[tx][ty];
    unsigned short h, l;
    split2(v, h, l);
    size_t base = (size_t)(n0 + ty) * KSPL + k0 + tx;
    O[base] = __ushort_as_bfloat16(h);
    O[base + CDIM] = __ushort_as_bfloat16(l);
    O[base + 2 * CDIM] = __ushort_as_bfloat16(h);
}

// ============================================================
// K3: projection GEMMs (HMMA, BM=128 x BN=64, 256 thr, 4x2 warps,
// 32x32 warp tiles, 3-stage).  z=0: pt [hi,hi,lo] ; z=1: pc [hi,lo,hi]
// ============================================================
__global__ void __launch_bounds__(256) proj_hmma(const float* __restrict__ bp,
                                                 const float* __restrict__ bc) {
    __shared__ __align__(16) __nv_bfloat16 sm[3 * (128 + 64) * SROWP];

    const int tid = threadIdx.x;
    const int z = blockIdx.z;
    const int m0 = blockIdx.y * 128;
    const int n0 = blockIdx.x * 64;

    const __nv_bfloat16* X = z ? g_xd_s : g_xt_s;
    const __nv_bfloat16* Wm = z ? g_Wc_s : g_Wp_s;
    const float* bias = z ? bc : bp;
    __nv_bfloat16* P = z ? g_pc_s : g_pt_s;

    float acc[8][4];
    #pragma unroll
    for (int i = 0; i < 8; i++)
        acc[i][0] = acc[i][1] = acc[i][2] = acc[i][3] = 0.0f;

    hmma_loop<128, 4, 2, 256>(X + (size_t)m0 * KSPL, Wm + (size_t)n0 * KSPL, sm, acc, tid);

    const int lane = tid & 31;
    const int warp = tid >> 5;
    const int wm = warp % 4;
    const int wn = warp / 4;

    #pragma unroll
    for (int im = 0; im < 2; im++) {
        #pragma unroll
        for (int jn = 0; jn < 4; jn++) {
            const float* c = acc[im * 4 + jn];
            int n = n0 + wn * 32 + jn * 8 + (lane & 3) * 2;
            float b0 = __ldg(&bias[n]), b1 = __ldg(&bias[n + 1]);
            int r0 = m0 + wm * 32 + im * 16 + (lane >> 2);
            #pragma unroll
            for (int h = 0; h < 2; h++) {
                int m = r0 + h * 8;
                float v0 = c[2 * h + 0] + b0;
                float v1 = c[2 * h + 1] + b1;
                unsigned short h0, l0, h1, l1;
                split2(v0, h0, l0);
                split2(v1, h1, l1);
                uint32_t hp = (uint32_t)h0 | ((uint32_t)h1 << 16);
                uint32_t lp = (uint32_t)l0 | ((uint32_t)l1 << 16);
                size_t rowoff = (size_t)m * KSPL + n;
                if (z == 0) {   // pt: [hi, hi, lo]
                    *reinterpret_cast<uint32_t*>(P + rowoff) = hp;
                    *reinterpret_cast<uint32_t*>(P + rowoff + CDIM) = hp;
                    *reinterpret_cast<uint32_t*>(P + rowoff + 2 * CDIM) = lp;
                } else {        // pc: [hi, lo, hi]
                    *reinterpret_cast<uint32_t*>(P + rowoff) = hp;
                    *reinterpret_cast<uint32_t*>(P + rowoff + CDIM) = lp;
                    *reinterpret_cast<uint32_t*>(P + rowoff + 2 * CDIM) = hp;
                }
            }
        }
    }
}

// ============================================================
// K4: score GEMM (HMMA, 64x64 tiles, 256 thr, 2x4 warps, 3-stage)
// ============================================================
__global__ void __launch_bounds__(256) score_hmma() {
    __shared__ __align__(16) __nv_bfloat16 sm[3 * (64 + 64) * SROWP];

    const int tid = threadIdx.x;
    const int b = blockIdx.z;
    const int i0 = blockIdx.y * 64;
    const int j0 = blockIdx.x * 64;

    const __nv_bfloat16* A = g_pt_s + (size_t)(b * LDIM + i0) * KSPL;
    const __nv_bfloat16* B = g_pc_s + (size_t)(b * LDIM + j0) * KSPL;

    float acc[4][4];
    #pragma unroll
    for (int i = 0; i < 4; i++)
        acc[i][0] = acc[i][1] = acc[i][2] = acc[i][3] = 0.0f;

    hmma_loop<64, 2, 4, 256>(A, B, sm, acc, tid);

    const int lane = tid & 31;
    const int warp = tid >> 5;
    const int wm = warp % 2;
    const int wn = warp / 2;

    float lsum = 0.0f;
    float* Sb = g_scores + ((size_t)b << 16);
    #pragma unroll
    for (int im = 0; im < 2; im++) {
        #pragma unroll
        for (int jn = 0; jn < 2; jn++) {
            const float* c = acc[im * 2 + jn];
            int j = j0 + wn * 16 + jn * 8 + (lane & 3) * 2;
            int r0 = i0 + wm * 32 + im * 16 + (lane >> 2);
            #pragma unroll
            for (int h = 0; h < 2; h++) {
                int i = r0 + h * 8;
                float s0 = sigmoid_fast(c[2 * h + 0]);
                float s1 = sigmoid_fast(c[2 * h + 1]);
                *reinterpret_cast<float2*>(Sb + (size_t)i * LDIM + j) =
                    make_float2(s0, s1);
                lsum += s0 + s1;
            }
        }
    }
    #pragma unroll
    for (int off = 16; off; off >>= 1)
        lsum += __shfl_xor_sync(0xFFFFFFFFu, lsum, off);
    __shared__ float red[8];
    if (lane == 0) red[warp] = lsum;
    __syncthreads();
    if (tid == 0) {
        float s = 0.0f;
        #pragma unroll
        for (int w = 0; w < 8; w++) s += red[w];
        atomicAdd(&g_Ssum[b], s);
    }
}

// ============================================================
// K5: cp_unnorm[b,c] = sum_{i,j} tanh(xd[b,i,c]*xt[b,j,c]) * scores[b,i,j]
// Packed-half tanh: tanh.approx.f16x2 -> 2 tanh per MUFU op.
// Products f32; tanh transit f16; accumulation f32.
// ============================================================
__global__ void __launch_bounds__(512) cp_kernel(const float* __restrict__ xd,
                                                 const float* __restrict__ xt) {
    const int b = blockIdx.y;
    const int i0 = blockIdx.x * 4;
    const int c = threadIdx.x;

    __shared__ float4 ws4[LDIM];
    {
        float* wsf = reinterpret_cast<float*>(ws4);
        const float* src = g_scores + (size_t)b * LDIM * LDIM + (size_t)i0 * LDIM;
        for (int t = threadIdx.x; t < 4 * LDIM; t += 512) {
            int i = t >> 8, j = t & (LDIM - 1);
            wsf[(j << 2) | i] = src[i * LDIM + j];
        }
    }

    const float* xdp = xd + ((size_t)(b * LDIM + i0)) * CDIM + c;
    const float xd0 = xdp[0 * CDIM];
    const float xd1 = xdp[1 * CDIM];
    const float xd2 = xdp[2 * CDIM];
    const float xd3 = xdp[3 * CDIM];
    __syncthreads();

    const float* xtp = xt + ((size_t)(b * LDIM)) * CDIM + c;
    float acc = 0.0f;
    #pragma unroll 4
    for (int j = 0; j < LDIM; j++) {
        float xtv = __ldg(&xtp[(size_t)j * CDIM]);
        float4 w = ws4[j];
        float2 t01 = tanh2_f16(xd0 * xtv, xd1 * xtv);
        float2 t23 = tanh2_f16(xd2 * xtv, xd3 * xtv);
        acc = fmaf(t01.x, w.x, acc);
        acc = fmaf(t01.y, w.y, acc);
        acc = fmaf(t23.x, w.z, acc);
        acc = fmaf(t23.y, w.w, acc);
    }
    atomicAdd(&g_cp[b * CDIM + c], acc);
}

// ============================================================
// K6: out[b,o] += (cp[b,:]/S_b) @ Wf[:,o]
// ============================================================
__global__ void out_gemm(const float* __restrict__ Wf, float* __restrict__ out) {
    const int b = blockIdx.x;
    const int c0 = blockIdx.y * 128;
    const int o = threadIdx.x;

    __shared__ float cps[128];
    float inv = __fdividef(1.0f, g_Ssum[b]);
    if (threadIdx.x < 128)
        cps[threadIdx.x] = g_cp[b * CDIM + c0 + threadIdx.x] * inv;
    __syncthreads();

    float acc = 0.0f;
    #pragma unroll 8
    for (int cc = 0; cc < 128; cc++)
        acc = fmaf(cps[cc], Wf[(c0 + cc) * ODIM + o], acc);
    atomicAdd(&out[b * ODIM + o], acc);
}

// ============================================================
extern "C" void kernel_launch(void* const* d_in, const int* in_sizes, int n_in,
                              void* d_out, int out_size) {
    const float* xd = (const float*)d_in[0];
    const float* xt = (const float*)d_in[1];
    const float* Wc = (const float*)d_in[2];
    const float* bc = (const float*)d_in[3];
    const float* Wp = (const float*)d_in[4];
    const float* bp = (const float*)d_in[5];
    const float* Wf = (const float*)d_in[6];
    const float* bf = (const float*)d_in[7];
    float* out = (float*)d_out;

    init_kernel<<<8, 512>>>(bf, out);
    split_x_kernel<<<dim3(MTOT * CDIM / 4 / 256, 1, 2), 256>>>(xt, xd);
    split_w_kernel<<<dim3(16, 16, 2), dim3(32, 32)>>>(Wp, Wc);
    proj_hmma<<<dim3(CDIM / 64, MTOT / 128, 2), 256>>>(bp, bc);
    score_hmma<<<dim3(LDIM / 64, LDIM / 64, BDIM), 256>>>();
    cp_kernel<<<dim3(LDIM / 4, BDIM), 512>>>(xd, xt);
    out_gemm<<<dim3(BDIM, 4), 512>>>(Wf, out);
}

// round 17
// speedup vs baseline: 1.0715x; 1.0715x over previous
#include <cuda_runtime.h>
#include <cuda_bf16.h>
#include <cstdint>

#define BDIM 8
#define LDIM 256
#define CDIM 512
#define ODIM 512
#define MTOT (BDIM * LDIM)   // 2048
#define KSPL 1536            // 3*CDIM split-K
#define SROWP 72             // smem row stride (64 + 8 pad) bf16

// -------- scratch (static device globals; no allocation) --------
__device__ __align__(16) __nv_bfloat16 g_xt_s[MTOT * KSPL];   // relu(xt) split [hi,hi,lo]
__device__ __align__(16) __nv_bfloat16 g_xd_s[MTOT * KSPL];   // relu(xd) split [hi,hi,lo]
__device__ __align__(16) __nv_bfloat16 g_Wp_s[CDIM * KSPL];   // Wp^T split [hi,lo,hi]
__device__ __align__(16) __nv_bfloat16 g_Wc_s[CDIM * KSPL];   // Wc^T split [hi,lo,hi]
__device__ __align__(16) __nv_bfloat16 g_pt_s[MTOT * KSPL];   // pt split [hi,hi,lo]
__device__ __align__(16) __nv_bfloat16 g_pc_s[MTOT * KSPL];   // pc split [hi,lo,hi]
__device__ float g_scores[BDIM * LDIM * LDIM];
__device__ float g_Ssum[BDIM];
__device__ float g_cp[BDIM * CDIM];

// -------- transcendentals --------
__device__ __forceinline__ float tanh_mufu(float x) {
    float y;
    asm("tanh.approx.f32 %0, %1;" : "=f"(y) : "f"(x));
    return y;
}
__device__ __forceinline__ float sigmoid_fast(float x) {
    return __fdividef(1.0f, 1.0f + __expf(-x));
}

// -------- helpers --------
__device__ __forceinline__ uint32_t smem_u32(const void* p) {
    uint32_t a;
    asm("{ .reg .u64 t; cvta.to.shared.u64 t, %1; cvt.u32.u64 %0, t; }" : "=r"(a) : "l"(p));
    return a;
}
__device__ __forceinline__ void ldsm4(uint32_t* r, uint32_t addr) {
    asm volatile("ldmatrix.sync.aligned.m8n8.x4.shared.b16 {%0,%1,%2,%3}, [%4];"
                 : "=r"(r[0]), "=r"(r[1]), "=r"(r[2]), "=r"(r[3]) : "r"(addr));
}
__device__ __forceinline__ void mma_bf16(float* c, const uint32_t* a,
                                         uint32_t b0, uint32_t b1) {
    asm volatile(
        "mma.sync.aligned.m16n8k16.row.col.f32.bf16.bf16.f32 "
        "{%0,%1,%2,%3}, {%4,%5,%6,%7}, {%8,%9}, {%0,%1,%2,%3};"
        : "+f"(c[0]), "+f"(c[1]), "+f"(c[2]), "+f"(c[3])
        : "r"(a[0]), "r"(a[1]), "r"(a[2]), "r"(a[3]), "r"(b0), "r"(b1));
}
__device__ __forceinline__ void cp_async16(uint32_t dst, const void* src) {
    asm volatile("cp.async.ca.shared.global [%0], [%1], 16;" :: "r"(dst), "l"(src));
}
#define CP_COMMIT() asm volatile("cp.async.commit_group;" ::: "memory")
#define CP_WAIT1()  asm volatile("cp.async.wait_group 1;" ::: "memory")
#define CP_WAIT0()  asm volatile("cp.async.wait_group 0;" ::: "memory")

__device__ __forceinline__ void split2(float v, unsigned short& h, unsigned short& l) {
    __nv_bfloat16 hb = __float2bfloat16(v);
    __nv_bfloat16 lb = __float2bfloat16(v - __bfloat162float(hb));
    h = __bfloat16_as_ushort(hb);
    l = __bfloat16_as_ushort(lb);
}

// ============================================================
// HMMA mainloop: C[BM,64] += A[BM,K'] . B[64,K']^T over K'=1536, BK=64,
// 3-stage cp.async pipeline, ONE __syncthreads per chunk.
// NWM x NWN warp grid; warp tile (BM/NWM) x (64/NWN).
// ============================================================
template <int BM, int NWM, int NWN, int NT>
__device__ __forceinline__ void hmma_loop(
        const __nv_bfloat16* __restrict__ A0,
        const __nv_bfloat16* __restrict__ B0,
        __nv_bfloat16* sm, float (*acc)[4], int tid) {
    constexpr int MI = BM / NWM / 16;
    constexpr int NJ = 64 / NWN / 8;
    constexpr int NJ2 = NJ / 2;
    constexpr int STAGE = (BM + 64) * SROWP;
    constexpr int NLD = (BM + 64) * 8;
    constexpr int LPT = NLD / NT;
    constexpr int NCH = KSPL / 64;

    const int lane = tid & 31;
    const int warp = tid >> 5;
    const int wm = warp % NWM;
    const int wn = warp / NWM;
    const uint32_t base = smem_u32(sm);

    auto issue = [&](int s, int c) {
        #pragma unroll
        for (int q = 0; q < LPT; q++) {
            int idx = tid + q * NT;
            int matB = (idx >= BM * 8);
            int rem = matB ? (idx - BM * 8) : idx;
            int row = rem >> 3;
            int kq = rem & 7;
            const __nv_bfloat16* g = (matB ? B0 : A0) + (size_t)row * KSPL + c * 64 + kq * 8;
            uint32_t d = base + (uint32_t)(s * STAGE + matB * (BM * SROWP)
                                           + row * SROWP + kq * 8) * 2;
            cp_async16(d, g);
        }
        CP_COMMIT();
    };

    issue(0, 0);
    issue(1, 1);

    for (int c = 0; c < NCH; c++) {
        const int s = c % 3;
        if (c + 1 < NCH) CP_WAIT1(); else CP_WAIT0();
        __syncthreads();
        if (c + 2 < NCH) issue((c + 2) % 3, c + 2);

        const uint32_t aBase = base + (uint32_t)(s * STAGE) * 2;
        const uint32_t bBase = aBase + (uint32_t)(BM * SROWP) * 2;
        #pragma unroll
        for (int kk = 0; kk < 64; kk += 16) {
            uint32_t af[MI][4];
            #pragma unroll
            for (int im = 0; im < MI; im++) {
                int row = wm * (BM / NWM) + im * 16 + (lane & 15);
                ldsm4(af[im], aBase + (uint32_t)(row * SROWP + kk + (lane >> 4) * 8) * 2);
            }
            #pragma unroll
            for (int j2 = 0; j2 < NJ2; j2++) {
                uint32_t bfr[4];
                int row = wn * (64 / NWN) + j2 * 16 + (lane & 15);
                ldsm4(bfr, bBase + (uint32_t)(row * SROWP + kk + (lane >> 4) * 8) * 2);
                #pragma unroll
                for (int im = 0; im < MI; im++) {
                    mma_bf16(acc[im * NJ + 2 * j2 + 0], af[im], bfr[0], bfr[2]);
                    mma_bf16(acc[im * NJ + 2 * j2 + 1], af[im], bfr[1], bfr[3]);
                }
            }
        }
    }
    __syncthreads();
}

// ============================================================
// K1: split X (with relu) -> [hi, hi, lo] bf16, K'=1536.
// Also performs init (zero Ssum/cp, seed out with bias) in block 0.
// ============================================================
__global__ void split_x_kernel(const float* __restrict__ xt, const float* __restrict__ xd,
                               const float* __restrict__ bf, float* __restrict__ out) {
    if (blockIdx.z == 0 && blockIdx.x < 16) {
        int idx = blockIdx.x * blockDim.x + threadIdx.x;   // 0..4095
        if (idx < BDIM) g_Ssum[idx] = 0.0f;
        if (idx < BDIM * CDIM) {
            g_cp[idx] = 0.0f;
            out[idx] = bf[idx & (ODIM - 1)];
        }
    }
    const float* X = blockIdx.z ? xd : xt;
    __nv_bfloat16* O = blockIdx.z ? g_xd_s : g_xt_s;
    int gid = blockIdx.x * blockDim.x + threadIdx.x;
    if (gid >= MTOT * CDIM / 4) return;
    int m = gid >> 7;
    int k4 = (gid & 127) * 4;
    float4 v = *reinterpret_cast<const float4*>(X + (size_t)m * CDIM + k4);
    float vv[4] = {fmaxf(v.x, 0.f), fmaxf(v.y, 0.f), fmaxf(v.z, 0.f), fmaxf(v.w, 0.f)};
    unsigned short h[4], l[4];
    #pragma unroll
    for (int i = 0; i < 4; i++) split2(vv[i], h[i], l[i]);
    uint2 hp = make_uint2((uint32_t)h[0] | ((uint32_t)h[1] << 16),
                          (uint32_t)h[2] | ((uint32_t)h[3] << 16));
    uint2 lp = make_uint2((uint32_t)l[0] | ((uint32_t)l[1] << 16),
                          (uint32_t)l[2] | ((uint32_t)l[3] << 16));
    size_t base = (size_t)m * KSPL + k4;
    *reinterpret_cast<uint2*>(O + base) = hp;
    *reinterpret_cast<uint2*>(O + base + CDIM) = hp;
    *reinterpret_cast<uint2*>(O + base + 2 * CDIM) = lp;
}

// ============================================================
// K2: split W with transpose: W[k,n] -> Wsplit[n,k'] segs [hi, lo, hi]
// ============================================================
__global__ void split_w_kernel(const float* __restrict__ Wp, const float* __restrict__ Wc) {
    const float* W = blockIdx.z ? Wc : Wp;
    __nv_bfloat16* O = blockIdx.z ? g_Wc_s : g_Wp_s;
    __shared__ float tile[32][33];
    int k0 = blockIdx.x * 32, n0 = blockIdx.y * 32;
    int tx = threadIdx.x, ty = threadIdx.y;
    tile[ty][tx] = W[(size_t)(k0 + ty) * CDIM + n0 + tx];
    __syncthreads();
    float v = tile[tx][ty];
    unsigned short h, l;
    split2(v, h, l);
    size_t base = (size_t)(n0 + ty) * KSPL + k0 + tx;
    O[base] = __ushort_as_bfloat16(h);
    O[base + CDIM] = __ushort_as_bfloat16(l);
    O[base + 2 * CDIM] = __ushort_as_bfloat16(h);
}

// ============================================================
// K3: projection GEMMs (HMMA, BM=128 x BN=64, 128 thr, 2x2 warps,
// 64x32 warp tiles, 3-stage).  z=0: pt [hi,hi,lo] ; z=1: pc [hi,lo,hi]
// ============================================================
__global__ void __launch_bounds__(128) proj_hmma(const float* __restrict__ bp,
                                                 const float* __restrict__ bc) {
    __shared__ __align__(16) __nv_bfloat16 sm[3 * (128 + 64) * SROWP];   // ~83 KB

    const int tid = threadIdx.x;
    const int z = blockIdx.z;
    const int m0 = blockIdx.y * 128;
    const int n0 = blockIdx.x * 64;

    const __nv_bfloat16* X = z ? g_xd_s : g_xt_s;
    const __nv_bfloat16* Wm = z ? g_Wc_s : g_Wp_s;
    const float* bias = z ? bc : bp;
    __nv_bfloat16* P = z ? g_pc_s : g_pt_s;

    float acc[16][4];   // MI=4, NJ=4
    #pragma unroll
    for (int i = 0; i < 16; i++)
        acc[i][0] = acc[i][1] = acc[i][2] = acc[i][3] = 0.0f;

    hmma_loop<128, 2, 2, 128>(X + (size_t)m0 * KSPL, Wm + (size_t)n0 * KSPL, sm, acc, tid);

    const int lane = tid & 31;
    const int warp = tid >> 5;
    const int wm = warp % 2;    // 64-row group
    const int wn = warp / 2;    // 32-col group

    #pragma unroll
    for (int im = 0; im < 4; im++) {
        #pragma unroll
        for (int jn = 0; jn < 4; jn++) {
            const float* c = acc[im * 4 + jn];
            int n = n0 + wn * 32 + jn * 8 + (lane & 3) * 2;
            float b0 = __ldg(&bias[n]), b1 = __ldg(&bias[n + 1]);
            int r0 = m0 + wm * 64 + im * 16 + (lane >> 2);
            #pragma unroll
            for (int h = 0; h < 2; h++) {
                int m = r0 + h * 8;
                float v0 = c[2 * h + 0] + b0;
                float v1 = c[2 * h + 1] + b1;
                unsigned short h0, l0, h1, l1;
                split2(v0, h0, l0);
                split2(v1, h1, l1);
                uint32_t hp = (uint32_t)h0 | ((uint32_t)h1 << 16);
                uint32_t lp = (uint32_t)l0 | ((uint32_t)l1 << 16);
                size_t rowoff = (size_t)m * KSPL + n;
                if (z == 0) {   // pt: [hi, hi, lo]
                    *reinterpret_cast<uint32_t*>(P + rowoff) = hp;
                    *reinterpret_cast<uint32_t*>(P + rowoff + CDIM) = hp;
                    *reinterpret_cast<uint32_t*>(P + rowoff + 2 * CDIM) = lp;
                } else {        // pc: [hi, lo, hi]
                    *reinterpret_cast<uint32_t*>(P + rowoff) = hp;
                    *reinterpret_cast<uint32_t*>(P + rowoff + CDIM) = lp;
                    *reinterpret_cast<uint32_t*>(P + rowoff + 2 * CDIM) = hp;
                }
            }
        }
    }
}

// ============================================================
// K4: score GEMM (HMMA, 64x64 tiles, 128 thr, 2x2 warps, 32x32 warp tiles)
// ============================================================
__global__ void __launch_bounds__(128) score_hmma() {
    __shared__ __align__(16) __nv_bfloat16 sm[3 * (64 + 64) * SROWP];

    const int tid = threadIdx.x;
    const int b = blockIdx.z;
    const int i0 = blockIdx.y * 64;
    const int j0 = blockIdx.x * 64;

    const __nv_bfloat16* A = g_pt_s + (size_t)(b * LDIM + i0) * KSPL;
    const __nv_bfloat16* B = g_pc_s + (size_t)(b * LDIM + j0) * KSPL;

    float acc[8][4];   // MI=2, NJ=4
    #pragma unroll
    for (int i = 0; i < 8; i++)
        acc[i][0] = acc[i][1] = acc[i][2] = acc[i][3] = 0.0f;

    hmma_loop<64, 2, 2, 128>(A, B, sm, acc, tid);

    const int lane = tid & 31;
    const int warp = tid >> 5;
    const int wm = warp % 2;
    const int wn = warp / 2;

    float lsum = 0.0f;
    float* Sb = g_scores + ((size_t)b << 16);
    #pragma unroll
    for (int im = 0; im < 2; im++) {
        #pragma unroll
        for (int jn = 0; jn < 4; jn++) {
            const float* c = acc[im * 4 + jn];
            int j = j0 + wn * 32 + jn * 8 + (lane & 3) * 2;
            int r0 = i0 + wm * 32 + im * 16 + (lane >> 2);
            #pragma unroll
            for (int h = 0; h < 2; h++) {
                int i = r0 + h * 8;
                float s0 = sigmoid_fast(c[2 * h + 0]);
                float s1 = sigmoid_fast(c[2 * h + 1]);
                *reinterpret_cast<float2*>(Sb + (size_t)i * LDIM + j) =
                    make_float2(s0, s1);
                lsum += s0 + s1;
            }
        }
    }
    #pragma unroll
    for (int off = 16; off; off >>= 1)
        lsum += __shfl_xor_sync(0xFFFFFFFFu, lsum, off);
    __shared__ float red[4];
    if (lane == 0) red[warp] = lsum;
    __syncthreads();
    if (tid == 0) {
        float s = red[0] + red[1] + red[2] + red[3];
        atomicAdd(&g_Ssum[b], s);
    }
}

// ============================================================
// K5: cp_unnorm[b,c] = sum_{i,j} tanh(xd[b,i,c]*xt[b,j,c]) * scores[b,i,j]
// Pure f32 MUFU.TANH (proven at the MUFU floor).
// ============================================================
__global__ void __launch_bounds__(512) cp_kernel(const float* __restrict__ xd,
                                                 const float* __restrict__ xt) {
    const int b = blockIdx.y;
    const int i0 = blockIdx.x * 4;
    const int c = threadIdx.x;

    __shared__ float4 ws4[LDIM];
    {
        float* wsf = reinterpret_cast<float*>(ws4);
        const float* src = g_scores + (size_t)b * LDIM * LDIM + (size_t)i0 * LDIM;
        for (int t = threadIdx.x; t < 4 * LDIM; t += 512) {
            int i = t >> 8, j = t & (LDIM - 1);
            wsf[(j << 2) | i] = src[i * LDIM + j];
        }
    }

    const float* xdp = xd + ((size_t)(b * LDIM + i0)) * CDIM + c;
    const float xd0 = xdp[0 * CDIM];
    const float xd1 = xdp[1 * CDIM];
    const float xd2 = xdp[2 * CDIM];
    const float xd3 = xdp[3 * CDIM];
    __syncthreads();

    const float* xtp = xt + ((size_t)(b * LDIM)) * CDIM + c;
    float acc = 0.0f;
    #pragma unroll 4
    for (int j = 0; j < LDIM; j++) {
        float xtv = __ldg(&xtp[(size_t)j * CDIM]);
        float4 w = ws4[j];
        acc = fmaf(tanh_mufu(xd0 * xtv), w.x, acc);
        acc = fmaf(tanh_mufu(xd1 * xtv), w.y, acc);
        acc = fmaf(tanh_mufu(xd2 * xtv), w.z, acc);
        acc = fmaf(tanh_mufu(xd3 * xtv), w.w, acc);
    }
    atomicAdd(&g_cp[b * CDIM + c], acc);
}

// ============================================================
// K6: out[b,o] += (cp[b,:]/S_b) @ Wf[:,o]
// ============================================================
__global__ void out_gemm(const float* __restrict__ Wf, float* __restrict__ out) {
    const int b = blockIdx.x;
    const int c0 = blockIdx.y * 128;
    const int o = threadIdx.x;

    __shared__ float cps[128];
    float inv = __fdividef(1.0f, g_Ssum[b]);
    if (threadIdx.x < 128)
        cps[threadIdx.x] = g_cp[b * CDIM + c0 + threadIdx.x] * inv;
    __syncthreads();

    float acc = 0.0f;
    #pragma unroll 8
    for (int cc = 0; cc < 128; cc++)
        acc = fmaf(cps[cc], Wf[(c0 + cc) * ODIM + o], acc);
    atomicAdd(&out[b * ODIM + o], acc);
}

// ============================================================
extern "C" void kernel_launch(void* const* d_in, const int* in_sizes, int n_in,
                              void* d_out, int out_size) {
    const float* xd = (const float*)d_in[0];
    const float* xt = (const float*)d_in[1];
    const float* Wc = (const float*)d_in[2];
    const float* bc = (const float*)d_in[3];
    const float* Wp = (const float*)d_in[4];
    const float* bp = (const float*)d_in[5];
    const float* Wf = (const float*)d_in[6];
    const float* bf = (const float*)d_in[7];
    float* out = (float*)d_out;

    split_x_kernel<<<dim3(MTOT * CDIM / 4 / 256, 1, 2), 256>>>(xt, xd, bf, out);
    split_w_kernel<<<dim3(16, 16, 2), dim3(32, 32)>>>(Wp, Wc);
    proj_hmma<<<dim3(CDIM / 64, MTOT / 128, 2), 128>>>(bp, bc);
    score_hmma<<<dim3(LDIM / 64, LDIM / 64, BDIM), 128>>>();
    cp_kernel<<<dim3(LDIM / 4, BDIM), 512>>>(xd, xt);
    out_gemm<<<dim3(BDIM, 4), 512>>>(Wf, out);
}